// round 3
// baseline (speedup 1.0000x reference)
#include <cuda_runtime.h>

// Reverse cummax along axis 1 of [B=16, H=128, W=128, C=256] fp32.
// out[b,h,w,c] = max_{h'>=h} in[b,h',w,c]
//
// One thread per (b, w, c4) float4 column; walks h = 127..0 with a
// register running max. Batched: 8 independent LDG.128 (__ldcs, evict-first)
// issued before the 8 max+STG.128 (__stcs), maximizing per-warp MLP.
// Pure streaming: 256MB read + 256MB write, zero reuse.

static constexpr int B = 16;
static constexpr int H = 128;
static constexpr int W = 128;
static constexpr int C = 256;
static constexpr int C4 = C / 4;                 // 64 float4 per (w) row
static constexpr int PLANE4 = W * C4;            // 8192 float4 per (b,h) slice
static constexpr int HSTRIDE4 = PLANE4;
static constexpr int NCOL = B * W * C4;          // 131072 columns
static constexpr int BATCH = 8;                  // h-steps per load/store phase

__global__ __launch_bounds__(256) void suffix_cummax_kernel(
    const float4* __restrict__ in, float4* __restrict__ out)
{
    int col = blockIdx.x * blockDim.x + threadIdx.x;  // grid covers exactly NCOL

    // col -> (b, w, c4): c4 fastest
    int c4 = col & (C4 - 1);
    int w  = (col >> 6) & (W - 1);       // C4 = 2^6
    int b  = col >> 13;                  // W*C4 = 2^13

    long long base = (long long)b * H * PLANE4 + (long long)w * C4 + c4;

    const float4* ip = in  + base + (long long)(H - 1) * HSTRIDE4;
    float4*       op = out + base + (long long)(H - 1) * HSTRIDE4;

    float4 run;
    run.x = -__int_as_float(0x7f800000);  // -inf
    run.y = run.x; run.z = run.x; run.w = run.x;

    #pragma unroll 1
    for (int it = 0; it < H / BATCH; ++it) {
        float4 v[BATCH];
        // Phase 1: batch of independent loads (streaming, evict-first)
        #pragma unroll
        for (int j = 0; j < BATCH; ++j) {
            v[j] = __ldcs(ip - (long long)j * HSTRIDE4);
        }
        // Phase 2: running max + streaming stores
        #pragma unroll
        for (int j = 0; j < BATCH; ++j) {
            run.x = fmaxf(run.x, v[j].x);
            run.y = fmaxf(run.y, v[j].y);
            run.z = fmaxf(run.z, v[j].z);
            run.w = fmaxf(run.w, v[j].w);
            __stcs(op - (long long)j * HSTRIDE4, run);
        }
        ip -= (long long)BATCH * HSTRIDE4;
        op -= (long long)BATCH * HSTRIDE4;
    }
}

extern "C" void kernel_launch(void* const* d_in, const int* in_sizes, int n_in,
                              void* d_out, int out_size)
{
    const float4* in  = (const float4*)d_in[0];
    float4*       out = (float4*)d_out;

    int threads = 256;
    int blocks  = NCOL / threads;  // 512, exact
    suffix_cummax_kernel<<<blocks, threads>>>(in, out);
}